// round 9
// baseline (speedup 1.0000x reference)
#include <cuda_runtime.h>
#include <cstdint>

// LIF forward: X[B=128, T=32, N=8192] fp32 -> spikes fp32.
// R9: R8's phase-separated traffic (pure-read recurrence packing spikes into
// 4 uint32 bitmasks, then pure-write expansion) with the register blowup
// clamped: __launch_bounds__(256, 6) caps regs at 42, forcing ptxas to tile
// the read phase (~4 loads in flight) instead of keeping all 32 float4 live
// (R8: 111 regs, occ 21.5%). Clean single-variable test of whether
// de-interleaving reads from writes reduces DRAM bus-turnaround loss.

static constexpr int B = 128;
static constexpr int T = 32;
static constexpr int N = 8192;
static constexpr int N4 = N / 4;          // 2048 float4 columns
static constexpr int TOTAL4 = B * N4;     // 262144 float4 lanes
static constexpr int TPB = 256;

__global__ __launch_bounds__(TPB, 6) void lif_kernel(const float4* __restrict__ X,
                                                     float4* __restrict__ out) {
    int idx = blockIdx.x * TPB + threadIdx.x;  // 0 .. TOTAL4-1

    int b = idx / N4;
    int n4 = idx - b * N4;

    const float4* xp = X + (size_t)b * T * N4 + n4;
    float4* op = out + (size_t)b * T * N4 + n4;

    float4 m = make_float4(0.f, 0.f, 0.f, 0.f);
    uint32_t b0 = 0, b1 = 0, b2 = 0, b3 = 0;  // spike bitmasks, bit t = plane t

    // ---- Phase 1: pure read + recurrence, spikes packed to bits ----
#pragma unroll
    for (int t = 0; t < T; t++) {
        float4 x = xp[(size_t)t * N4];

        m.x = m.x + (x.x - m.x) * 0.5f;
        m.y = m.y + (x.y - m.y) * 0.5f;
        m.z = m.z + (x.z - m.z) * 0.5f;
        m.w = m.w + (x.w - m.w) * 0.5f;

        uint32_t s0 = (m.x > 1.0f) ? 1u : 0u;
        uint32_t s1 = (m.y > 1.0f) ? 1u : 0u;
        uint32_t s2 = (m.z > 1.0f) ? 1u : 0u;
        uint32_t s3 = (m.w > 1.0f) ? 1u : 0u;

        b0 |= s0 << t;
        b1 |= s1 << t;
        b2 |= s2 << t;
        b3 |= s3 << t;

        if (s0) m.x = 0.0f;
        if (s1) m.y = 0.0f;
        if (s2) m.z = 0.0f;
        if (s3) m.w = 0.0f;
    }

    // ---- Phase 2: pure write, expand bits to fp32 spikes ----
#pragma unroll
    for (int t = 0; t < T; t++) {
        float4 s;
        s.x = ((b0 >> t) & 1u) ? 1.0f : 0.0f;
        s.y = ((b1 >> t) & 1u) ? 1.0f : 0.0f;
        s.z = ((b2 >> t) & 1u) ? 1.0f : 0.0f;
        s.w = ((b3 >> t) & 1u) ? 1.0f : 0.0f;
        op[(size_t)t * N4] = s;
    }
}

extern "C" void kernel_launch(void* const* d_in, const int* in_sizes, int n_in,
                              void* d_out, int out_size) {
    const float4* X = (const float4*)d_in[0];
    float4* out = (float4*)d_out;
    lif_kernel<<<TOTAL4 / TPB, TPB>>>(X, out);
}

// round 10
// speedup vs baseline: 1.9953x; 1.9953x over previous
#include <cuda_runtime.h>

// LIF forward: X[B=128, T=32, N=8192] fp32 -> spikes fp32 (same shape).
// Per (b, n): mem = mem + (x_t - mem)/2 ; spike = mem > 1 ; mem = 0 on spike.
//
// FINAL. This problem is a touch-once 256 MiB stream (128 MiB read +
// 128 MiB write, ~3 flops/elem). Verified across 7 structurally different
// implementations (scalar LDG/STG, 2-col MLP, explicit load batching,
// cp.async.bulk/TMA mbarrier pipeline, reg-capped single-wave, streaming
// .cs hints, bitpacked read/write phase separation): every well-formed
// variant converges to kernel 38.0-40.4 us = ~7.0 TB/s effective
// steady-state HBM throughput = 88% of the 8 TB/s spec — the practical
// ceiling for an interleaved 50/50 R/W stream (read<->write bus turnaround
// accounts for the remainder). Phase-separating the traffic to avoid
// turnaround fails structurally: it needs 32 live float4 per thread, which
// either collapses occupancy (111 regs, 21.5% occ) or spills to local
// (+70% DRAM traffic, 90 us).
//
// Layout: 1 thread = 1 float4 column (4 consecutive n); walks t with
// stride N/4 -> every warp issues perfectly coalesced 128B transactions.
// Full T=32 unroll lets ptxas batch independent LDG.128s ahead of the
// serial 2-FMA-per-step recurrence chain. regs=39, occ ~63%, which is
// sufficient to saturate the mixed-stream DRAM ceiling.

static constexpr int B = 128;
static constexpr int T = 32;
static constexpr int N = 8192;
static constexpr int N4 = N / 4;          // float4 columns per plane
static constexpr int TOTAL4 = B * N4;     // 262144 float4 lanes
static constexpr int TPB = 256;

__device__ __forceinline__ float4 step4(float4& m, const float4 x) {
    // exact reference rounding: mem += (x - mem) * 0.5f
    m.x = m.x + (x.x - m.x) * 0.5f;
    m.y = m.y + (x.y - m.y) * 0.5f;
    m.z = m.z + (x.z - m.z) * 0.5f;
    m.w = m.w + (x.w - m.w) * 0.5f;
    float4 s;
    s.x = (m.x > 1.0f) ? 1.0f : 0.0f;
    s.y = (m.y > 1.0f) ? 1.0f : 0.0f;
    s.z = (m.z > 1.0f) ? 1.0f : 0.0f;
    s.w = (m.w > 1.0f) ? 1.0f : 0.0f;
    // hard reset to 0 where spiked
    if (s.x != 0.0f) m.x = 0.0f;
    if (s.y != 0.0f) m.y = 0.0f;
    if (s.z != 0.0f) m.z = 0.0f;
    if (s.w != 0.0f) m.w = 0.0f;
    return s;
}

__global__ __launch_bounds__(TPB) void lif_kernel(const float4* __restrict__ X,
                                                  float4* __restrict__ out) {
    int idx = blockIdx.x * TPB + threadIdx.x;  // 0 .. TOTAL4-1
    if (idx >= TOTAL4) return;

    int b = idx / N4;
    int n4 = idx - b * N4;

    const float4* xp = X + (size_t)b * T * N4 + n4;
    float4* op = out + (size_t)b * T * N4 + n4;

    float4 m = make_float4(0.f, 0.f, 0.f, 0.f);

#pragma unroll
    for (int t = 0; t < T; t++) {
        float4 x = xp[(size_t)t * N4];
        float4 s = step4(m, x);
        op[(size_t)t * N4] = s;
    }
}

extern "C" void kernel_launch(void* const* d_in, const int* in_sizes, int n_in,
                              void* d_out, int out_size) {
    const float4* X = (const float4*)d_in[0];
    float4* out = (float4*)d_out;
    lif_kernel<<<TOTAL4 / TPB, TPB>>>(X, out);
}